// round 14
// baseline (speedup 1.0000x reference)
#include <cuda_runtime.h>

#define DD 2048
#define PP 16000

typedef unsigned long long u64;

// Sketch structure extracted from C1/C2 each launch (deterministic).
__device__ int   g_idx1[DD], g_idx2[DD];
__device__ float g_sgn1[DD], g_sgn2[DD];

// ---------------------------------------------------------------------------
// Kernel E: one 256-thread CTA per C-row; early-exit scan in 8KB chunks
// (2 float4/thread), depth-1 prefetch of both loads, barrier-free flag poll.
// One nonzero per row -> race-free. Signals PDL dependents at exit.
// ---------------------------------------------------------------------------
__global__ void __launch_bounds__(256)
extract_kernel(const float4* __restrict__ C1, const float4* __restrict__ C2) {
    int d = blockIdx.x;                       // 0..4095
    const float4* rowp;
    int*  idx;
    float* sgn;
    int r;
    if (d < DD) { rowp = C1 + (size_t)d * 4000;        idx = g_idx1; sgn = g_sgn1; r = d; }
    else        { rowp = C2 + (size_t)(d - DD) * 4000; idx = g_idx2; sgn = g_sgn2; r = d - DD; }

    volatile __shared__ int found;
    if (threadIdx.x == 0) found = 0;
    __syncthreads();

    // 4000 float4 per row; 8 chunks of 512 float4 (2 per thread), depth-1 PF.
    int base = threadIdx.x;                   // chunk c: loads base, base+256
    float4 a0 = __ldcs(&rowp[base]);
    float4 a1 = __ldcs(&rowp[base + 256]);
#pragma unroll 1
    for (int c = 0; c < 8; c++) {
        int nb = base + 512;
        float4 b0 = make_float4(0.f, 0.f, 0.f, 0.f);
        float4 b1 = make_float4(0.f, 0.f, 0.f, 0.f);
        if (c < 7) {
            if (nb < 4000)       b0 = __ldcs(&rowp[nb]);
            if (nb + 256 < 4000) b1 = __ldcs(&rowp[nb + 256]);
        }
        int i0 = base, i1 = base + 256;
        if (i0 < 4000 &&
            (a0.x != 0.f || a0.y != 0.f || a0.z != 0.f || a0.w != 0.f)) {
            int e = i0 * 4;
            if      (a0.x != 0.f) { idx[r] = e;     sgn[r] = a0.x; }
            else if (a0.y != 0.f) { idx[r] = e + 1; sgn[r] = a0.y; }
            else if (a0.z != 0.f) { idx[r] = e + 2; sgn[r] = a0.z; }
            else                  { idx[r] = e + 3; sgn[r] = a0.w; }
            found = 1;
        }
        if (i1 < 4000 &&
            (a1.x != 0.f || a1.y != 0.f || a1.z != 0.f || a1.w != 0.f)) {
            int e = i1 * 4;
            if      (a1.x != 0.f) { idx[r] = e;     sgn[r] = a1.x; }
            else if (a1.y != 0.f) { idx[r] = e + 1; sgn[r] = a1.y; }
            else if (a1.z != 0.f) { idx[r] = e + 2; sgn[r] = a1.z; }
            else                  { idx[r] = e + 3; sgn[r] = a1.w; }
            found = 1;
        }
        if (found) break;                     // volatile read, warp-uniform
        a0 = b0; a1 = b1; base = nb;
    }

    // allow the dependent FFT kernel's prologue to overlap our tail
    asm volatile("griddepcontrol.launch_dependents;");
}

// ---------------------------------------------------------------------------
// Packed f32x2 helpers (Blackwell FFMA2 path — PTX only).
// ---------------------------------------------------------------------------
__device__ __forceinline__ u64 pk(float x, float y) {
    u64 u;
    asm("mov.b64 %0, {%1, %2};" : "=l"(u)
        : "r"(__float_as_uint(x)), "r"(__float_as_uint(y)));
    return u;
}
__device__ __forceinline__ u64 pk2(float2 a) { return pk(a.x, a.y); }
__device__ __forceinline__ float2 upk(u64 u) {
    unsigned lo, hi;
    asm("mov.b64 {%0, %1}, %2;" : "=r"(lo), "=r"(hi) : "l"(u));
    return make_float2(__uint_as_float(lo), __uint_as_float(hi));
}
__device__ __forceinline__ u64 padd(u64 a, u64 b) {
    u64 r; asm("add.rn.f32x2 %0, %1, %2;" : "=l"(r) : "l"(a), "l"(b)); return r;
}
__device__ __forceinline__ u64 pmul(u64 a, u64 b) {
    u64 r; asm("mul.rn.f32x2 %0, %1, %2;" : "=l"(r) : "l"(a), "l"(b)); return r;
}
__device__ __forceinline__ u64 pfma(u64 a, u64 b, u64 c) {
    u64 r; asm("fma.rn.f32x2 %0, %1, %2, %3;" : "=l"(r) : "l"(a), "l"(b), "l"(c)); return r;
}
__device__ __forceinline__ u64 psplat(float s) { return pk(s, s); }
__device__ __forceinline__ u64 psub(u64 a, u64 b) { return pfma(b, psplat(-1.0f), a); }
__device__ __forceinline__ u64 pcmul(u64 a, u64 b) {
    float2 af = upk(a), bf = upk(b);
    u64 u = pmul(pk(af.y, af.y), pk(bf.y, bf.x));   // {ay*by, ay*bx}
    float2 uf = upk(u);
    return pfma(pk(af.x, af.x), b, pk(-uf.x, uf.y));
}

// scalar complex helpers (Hermitian pass)
__device__ __forceinline__ float2 cmul(float2 a, float2 b) {
    return make_float2(a.x * b.x - a.y * b.y, a.x * b.y + a.y * b.x);
}

__device__ __constant__ int c_brev4[16] = {0,8,4,12,2,10,6,14,1,9,5,13,3,11,7,15};
__device__ __constant__ int c_brev3[8]  = {0,4,2,6,1,5,3,7};

// cheap small divisions (valid for the ranges used)
__device__ __forceinline__ int div5(int x)  { return (x * 205) >> 10; }   // x < 1024
__device__ __forceinline__ int div25(int x) { return (x * 41)  >> 10; }   // x < 600
__device__ __forceinline__ int mod125_16k(int x, int& q) {                // x <= 16000
    q = (int)(((unsigned)x * 8389u) >> 20);
    return x - q * 125;
}
__device__ __forceinline__ int digrev125(int b) {
    int d12 = div5(b);
    int d2  = div25(b);
    int d0  = b - d12 * 5;
    int d1  = d12 - d2 * 5;
    return d0 * 25 + d1 * 5 + d2;
}
__device__ __forceinline__ int brev7(int a) { return (int)(__brev((unsigned)a) >> 25); }

// ---------------------------------------------------------------------------
// Fused radix-2 butterfly blocks (DIF, logical t-order), packed arithmetic.
// ---------------------------------------------------------------------------
__device__ __forceinline__ void bfly16(u64* X, int j, const float2* W128) {
#pragma unroll
    for (int ls = 8; ls >= 1; ls >>= 1) {
        int f = 8 / ls;
#pragma unroll
        for (int g = 0; g < 8 / ls; g++)
#pragma unroll
            for (int i = 0; i < ls; i++) {
                int t0 = g * 2 * ls + i, t1 = t0 + ls;
                u64 u = X[t0], v = X[t1];
                X[t0] = padd(u, v);
                X[t1] = pcmul(psub(u, v), pk2(W128[(j + 8 * i) * f]));
            }
    }
}

__device__ __forceinline__ void bfly8(u64* X, const float2* W128) {
#pragma unroll
    for (int ls = 4; ls >= 1; ls >>= 1) {
        int f = 64 / ls;
#pragma unroll
        for (int g = 0; g < 4 / ls; g++)
#pragma unroll
            for (int i = 0; i < ls; i++) {
                int t0 = g * 2 * ls + i, t1 = t0 + ls;
                u64 u = X[t0], v = X[t1];
                X[t0] = padd(u, v);
                if (ls == 1) X[t1] = psub(u, v);
                else         X[t1] = pcmul(psub(u, v), pk2(W128[i * f]));
            }
    }
}

// Winograd-style radix-5 DFT, packed, with output twiddles W125[r*e].
__device__ __forceinline__ void bfly5(u64* x, int e, const float2* W125) {
    const float C1 = 0.30901699437494745f;   // cos(2pi/5)
    const float C2 = -0.8090169943749473f;   // cos(4pi/5)
    const float S1 = 0.9510565162951535f;    // sin(2pi/5)
    const float S2 = 0.5877852522924731f;    // sin(4pi/5)
    u64 t1 = padd(x[1], x[4]);
    u64 t2 = padd(x[2], x[3]);
    u64 t3 = psub(x[1], x[4]);
    u64 t4 = psub(x[2], x[3]);
    u64 y0 = padd(x[0], padd(t1, t2));
    u64 a1 = pfma(t1, psplat(C1), pfma(t2, psplat(C2), x[0]));
    u64 a2 = pfma(t1, psplat(C2), pfma(t2, psplat(C1), x[0]));
    u64 b1 = pfma(t3, psplat(S1), pmul(t4, psplat(S2)));
    u64 b2 = pfma(t3, psplat(S2), pmul(t4, psplat(-S1)));
    float2 b1f = upk(b1), b2f = upk(b2);
    u64 ib1 = pk(b1f.y, -b1f.x);             // -i * b1
    u64 ib2 = pk(b2f.y, -b2f.x);
    u64 y1 = padd(a1, ib1);
    u64 y4 = psub(a1, ib1);
    u64 y2 = padd(a2, ib2);
    u64 y3 = psub(a2, ib2);
    if (e) {
        y1 = pcmul(y1, pk2(W125[e]));
        y2 = pcmul(y2, pk2(W125[2 * e]));
        y3 = pcmul(y3, pk2(W125[3 * e]));
        y4 = pcmul(y4, pk2(W125[4 * e]));
    }
    x[0] = y0; x[1] = y1; x[2] = y2; x[3] = y3; x[4] = y4;
}

// fused stages m=5 (tw 5j) and m=1 over 25 register-resident values.
__device__ __forceinline__ void bfly25_m5_m1(u64* y, const float2* W125) {
#pragma unroll
    for (int j = 0; j < 5; j++) {
        u64 x[5];
#pragma unroll
        for (int r = 0; r < 5; r++) x[r] = y[j + 5 * r];
        bfly5(x, 5 * j, W125);
#pragma unroll
        for (int r = 0; r < 5; r++) y[j + 5 * r] = x[r];
    }
#pragma unroll
    for (int g = 0; g < 5; g++) {
        bfly5(&y[5 * g], 0, W125);
    }
}

// fused stages m=5 and m=1 in the sigma-permuted layout, local index i = 5j+s.
__device__ __forceinline__ void bfly25_m5_m1_perm(u64* y, const float2* W125) {
#pragma unroll
    for (int j = 0; j < 5; j++) {
        bfly5(&y[5 * j], 5 * j, W125);
    }
#pragma unroll
    for (int s = 0; s < 5; s++) {
        u64 x[5];
#pragma unroll
        for (int j = 0; j < 5; j++) x[j] = y[s + 5 * j];
        bfly5(x, 0, W125);
#pragma unroll
        for (int j = 0; j < 5; j++) y[s + 5 * j] = x[j];
    }
}

#define NTHR 1024

// ---------------------------------------------------------------------------
// Forward FFT2, natural layout in -> sigma-permuted out. 4 passes.
// ---------------------------------------------------------------------------
__device__ void fft2_nat(float2* Z, const float2* W128, const float2* W125,
                         int tid) {
    // a-axis group 1: stages 64,32,16,8
    {
        int j = tid >> 7, col = tid & 127;
        if (col < 125) {
            u64 X[16];
#pragma unroll
            for (int t = 0; t < 16; t++) X[t] = pk2(Z[(j + 8 * t) * 125 + col]);
            bfly16(X, j, W128);
#pragma unroll
            for (int t = 0; t < 16; t++) Z[(j + 8 * t) * 125 + col] = upk(X[t]);
        }
    }
    __syncthreads();
    // a-axis group 2: stages 4,2,1
#pragma unroll
    for (int it = 0; it < 2; it++) {
        int idx = tid + it * NTHR;
        int g = idx >> 7, col = idx & 127;
        if (col < 125) {
            u64 X[8];
#pragma unroll
            for (int t = 0; t < 8; t++) X[t] = pk2(Z[(8 * g + t) * 125 + col]);
            bfly8(X, W128);
#pragma unroll
            for (int t = 0; t < 8; t++) Z[(8 * g + t) * 125 + col] = upk(X[t]);
        }
    }
    __syncthreads();
    // b-axis m=25: 128 a x 25 c
#pragma unroll
    for (int it = 0; it < 4; it++) {
        int idx = tid + it * NTHR;
        int a = idx >> 5, c = idx & 31;
        if (c < 25) {
            int base = a * 125 + c;
            u64 x[5];
#pragma unroll
            for (int r = 0; r < 5; r++) x[r] = pk2(Z[base + 25 * r]);
            bfly5(x, c, W125);
#pragma unroll
            for (int r = 0; r < 5; r++) Z[base + 25 * r] = upk(x[r]);
        }
    }
    __syncthreads();
    // b-axis fused m=5 & m=1: lane <-> a, warp-uniform t
    {
        int u = tid;
        if (u < 640) {
            int a = u & 127, t = u >> 7;
            int base = a * 125 + t * 25;
            u64 y[25];
#pragma unroll
            for (int i = 0; i < 25; i++) y[i] = pk2(Z[base + i]);
            bfly25_m5_m1(y, W125);
#pragma unroll
            for (int i = 0; i < 25; i++) Z[base + i] = upk(y[i]);
        }
    }
    __syncthreads();
}

// ---------------------------------------------------------------------------
// Kernel F: one CTA per batch row. PDL: waits for extract AFTER its prologue.
// ---------------------------------------------------------------------------
__global__ void __launch_bounds__(NTHR, 1)
mcb_fft_kernel(const float* __restrict__ x1,
               const float* __restrict__ x2,
               float* __restrict__ out) {
    extern __shared__ float2 sm[];
    float2* Z    = sm;                       // 16000
    float2* W128 = sm + 16000;               // 128
    float2* W125 = sm + 16128;               // 125
    float*  sOut = (float*)(sm + 16254);     // 16000 floats, 16B-aligned

    const int tid = threadIdx.x;
    const int row = blockIdx.x;

    // init: zero grid (float4), fill twiddle tables — independent of extract
    float4* Z4 = (float4*)Z;
#pragma unroll
    for (int it = 0; it < 8; it++) {
        int i = tid + it * NTHR;
        if (i < 8000) Z4[i] = make_float4(0.f, 0.f, 0.f, 0.f);
    }
    if (tid < 128) {
        float s, c;
        sincosf(-6.283185307179586f * (float)tid / 128.f, &s, &c);
        W128[tid] = make_float2(c, s);
    }
    {
        int k = tid - 128;
        if (k >= 0 && k < 125) {
            float s, c;
            sincosf(-6.283185307179586f * (float)k / 125.f, &s, &c);
            W125[k] = make_float2(c, s);
        }
    }

    // PDL: block here until the extract grid's writes are visible.
    asm volatile("griddepcontrol.wait;" ::: "memory");
    __syncthreads();

    // count-sketch scatter onto CRT-mapped 2-D grid (natural layout)
    const float* x1r = x1 + row * DD;
    const float* x2r = x2 + row * DD;
#pragma unroll
    for (int it = 0; it < 2; it++) {
        int d = tid + it * NTHR;
        int q1, q2;
        int n1 = g_idx1[d];
        float v1 = g_sgn1[d] * x1r[d];
        int b1 = mod125_16k(n1, q1);
        atomicAdd(&Z[(n1 & 127) * 125 + b1].x, v1);
        int n2 = g_idx2[d];
        float v2 = g_sgn2[d] * x2r[d];
        int b2 = mod125_16k(n2, q2);
        atomicAdd(&Z[(n2 & 127) * 125 + b2].y, v2);
    }
    __syncthreads();

    // forward FFT2 of z = y1 + i*y2; physical slot p holds Fz[sigma(p)]
    fft2_nat(Z, W128, W125, tid);

    // Hermitian unpack + pointwise product, enumerating LOGICAL k in [0, 8000].
    for (int k = tid; k <= 8000; k += NTHR) {
        int ka = k & 127;
        int q;
        int kb = mod125_16k(k, q);
        int p  = brev7(ka) * 125 + digrev125(kb);
        int kam = (128 - ka) & 127;
        int kbm = (kb == 0) ? 0 : 125 - kb;
        int pm  = brev7(kam) * 125 + digrev125(kbm);
        float2 zk = Z[p], zm = Z[pm];
        float2 f1 = make_float2(0.5f * (zk.x + zm.x),  0.5f * (zk.y - zm.y));
        float2 f2 = make_float2(0.5f * (zk.y + zm.y), -0.5f * (zk.x - zm.x));
        float2 g  = cmul(f1, f2);
        Z[p]  = make_float2(g.x, -g.y);     // conj(G[k])
        Z[pm] = g;                          // conj(G[-k]) = G[k]
    }
    __syncthreads();

    // ---- inverse via forward-on-conj in the sigma-permuted layout ----
    // a-axis group 1: logical rows j+8t at physical brev3(j)*16 + brev4(t)
    {
        int j = tid >> 7, col = tid & 127;
        if (col < 125) {
            int R0 = c_brev3[j] * 16;
            u64 X[16];
#pragma unroll
            for (int t = 0; t < 16; t++) X[t] = pk2(Z[(R0 + c_brev4[t]) * 125 + col]);
            bfly16(X, j, W128);
#pragma unroll
            for (int t = 0; t < 16; t++) Z[(R0 + c_brev4[t]) * 125 + col] = upk(X[t]);
        }
    }
    __syncthreads();
    // a-axis group 2: logical rows 8g+t at physical brev3(t)*16 + brev4(g)
#pragma unroll
    for (int it = 0; it < 2; it++) {
        int idx = tid + it * NTHR;
        int g = idx >> 7, col = idx & 127;
        if (col < 125) {
            int G = c_brev4[g];
            u64 X[8];
#pragma unroll
            for (int t = 0; t < 8; t++) X[t] = pk2(Z[(c_brev3[t] * 16 + G) * 125 + col]);
            bfly8(X, W128);
#pragma unroll
            for (int t = 0; t < 8; t++) Z[(c_brev3[t] * 16 + G) * 125 + col] = upk(X[t]);
        }
    }
    __syncthreads();
    // b-axis m=25: logical b = c + 25t -> physical (c%5)*25 + (c/5)*5 + t
#pragma unroll
    for (int it = 0; it < 4; it++) {
        int idx = tid + it * NTHR;
        int a = idx >> 5, c = idx & 31;
        if (c < 25) {
            int ch = div5(c), cl = c - ch * 5;
            int base = a * 125 + cl * 25 + ch * 5;
            u64 x[5];
#pragma unroll
            for (int r = 0; r < 5; r++) x[r] = pk2(Z[base + r]);
            bfly5(x, c, W125);
#pragma unroll
            for (int r = 0; r < 5; r++) Z[base + r] = upk(x[r]);
        }
    }
    __syncthreads();
    // b-axis fused m=5 & m=1; stage real part into sOut at natural CRT index.
    // lane <-> a mapping: 10625 % 32 == 1 -> sOut banks consecutive per lane.
    {
        const float scale = 1.0f / 16000.0f;
        int u = tid;
        if (u < 640) {
            int a = u & 127, t = u >> 7;
            int base = a * 125 + t;
            u64 y[25];
#pragma unroll
            for (int i = 0; i < 25; i++) y[i] = pk2(Z[base + 5 * i]);
            bfly25_m5_m1_perm(y, W125);
            int n = (a * 10625 + t * 5376) % 16000;
#pragma unroll
            for (int i = 0; i < 25; i++) {
                sOut[n] = upk(y[i]).x * scale;
                n += 10880;
                if (n >= 16000) n -= 16000;
            }
        }
    }
    __syncthreads();

    // coalesced output write
    {
        const float4* so4 = (const float4*)sOut;
        float4* og = (float4*)(out + row * PP);
#pragma unroll
        for (int it = 0; it < 4; it++) {
            int i = tid + it * NTHR;
            if (i < 4000) og[i] = so4[i];
        }
    }
}

// ---------------------------------------------------------------------------
// Launch (PDL: FFT kernel launched with programmatic stream serialization)
// ---------------------------------------------------------------------------
extern "C" void kernel_launch(void* const* d_in, const int* in_sizes, int n_in,
                              void* d_out, int out_size) {
    const float*  x1 = (const float*)d_in[0];
    const float*  x2 = (const float*)d_in[1];
    const float4* C1 = (const float4*)d_in[2];
    const float4* C2 = (const float4*)d_in[3];
    float* out = (float*)d_out;

    const int B = in_sizes[0] / DD;           // 128

    extract_kernel<<<2 * DD, 256>>>(C1, C2);

    const size_t smem = (size_t)16254 * sizeof(float2) + (size_t)PP * sizeof(float); // 194,032 B
    cudaFuncSetAttribute(mcb_fft_kernel,
                         cudaFuncAttributeMaxDynamicSharedMemorySize, (int)smem);

    cudaLaunchConfig_t cfg = {};
    cfg.gridDim = dim3(B, 1, 1);
    cfg.blockDim = dim3(NTHR, 1, 1);
    cfg.dynamicSmemBytes = smem;
    cudaLaunchAttribute attrs[1];
    attrs[0].id = cudaLaunchAttributeProgrammaticStreamSerialization;
    attrs[0].val.programmaticStreamSerializationAllowed = 1;
    cfg.attrs = attrs;
    cfg.numAttrs = 1;
    cudaLaunchKernelEx(&cfg, mcb_fft_kernel, x1, x2, out);
}

// round 15
// speedup vs baseline: 1.0078x; 1.0078x over previous
#include <cuda_runtime.h>

#define DD 2048
#define PP 16000

typedef unsigned long long u64;

// Sketch structure extracted from C1/C2 each launch (deterministic).
__device__ int   g_idx1[DD], g_idx2[DD];
__device__ float g_sgn1[DD], g_sgn2[DD];

// ---------------------------------------------------------------------------
// Kernel E: one 256-thread CTA scans TWO C-rows concurrently (interleaved
// independent load streams -> 2x memory-level parallelism at equal bytes).
// Early-exit per row via volatile shared flags; one nonzero per row ->
// single writer, flag races benign. Signals PDL dependents at exit.
// ---------------------------------------------------------------------------
__global__ void __launch_bounds__(256)
extract_kernel(const float4* __restrict__ C1, const float4* __restrict__ C2) {
    int pair = blockIdx.x;                    // 0..2047
    int d0 = 2 * pair, d1 = 2 * pair + 1;     // rows 0..4095

    const float4 *rp0, *rp1;
    int *ix0, *ix1;
    float *sg0, *sg1;
    int r0, r1;
    if (d0 < DD) { rp0 = C1 + (size_t)d0 * 4000;        ix0 = g_idx1; sg0 = g_sgn1; r0 = d0; }
    else         { rp0 = C2 + (size_t)(d0 - DD) * 4000; ix0 = g_idx2; sg0 = g_sgn2; r0 = d0 - DD; }
    if (d1 < DD) { rp1 = C1 + (size_t)d1 * 4000;        ix1 = g_idx1; sg1 = g_sgn1; r1 = d1; }
    else         { rp1 = C2 + (size_t)(d1 - DD) * 4000; ix1 = g_idx2; sg1 = g_sgn2; r1 = d1 - DD; }

    volatile __shared__ int f0, f1;
    if (threadIdx.x == 0) { f0 = 0; f1 = 0; }
    __syncthreads();

    // 4000 float4 per row; 16 chunks of 256 float4 per row, depth-1 prefetch.
    int base = threadIdx.x;
    float4 a0 = __ldcs(&rp0[base]);
    float4 a1 = __ldcs(&rp1[base]);
    bool done0 = false, done1 = false;
#pragma unroll 1
    for (int c = 0; c < 16; c++) {
        int nb = base + 256;
        float4 b0 = make_float4(0.f, 0.f, 0.f, 0.f);
        float4 b1 = make_float4(0.f, 0.f, 0.f, 0.f);
        if (c < 15 && nb < 4000) {
            if (!done0) b0 = __ldcs(&rp0[nb]);
            if (!done1) b1 = __ldcs(&rp1[nb]);
        }
        if (!done0 && base < 4000 &&
            (a0.x != 0.f || a0.y != 0.f || a0.z != 0.f || a0.w != 0.f)) {
            int e = base * 4;
            if      (a0.x != 0.f) { ix0[r0] = e;     sg0[r0] = a0.x; }
            else if (a0.y != 0.f) { ix0[r0] = e + 1; sg0[r0] = a0.y; }
            else if (a0.z != 0.f) { ix0[r0] = e + 2; sg0[r0] = a0.z; }
            else                  { ix0[r0] = e + 3; sg0[r0] = a0.w; }
            f0 = 1;
        }
        if (!done1 && base < 4000 &&
            (a1.x != 0.f || a1.y != 0.f || a1.z != 0.f || a1.w != 0.f)) {
            int e = base * 4;
            if      (a1.x != 0.f) { ix1[r1] = e;     sg1[r1] = a1.x; }
            else if (a1.y != 0.f) { ix1[r1] = e + 1; sg1[r1] = a1.y; }
            else if (a1.z != 0.f) { ix1[r1] = e + 2; sg1[r1] = a1.z; }
            else                  { ix1[r1] = e + 3; sg1[r1] = a1.w; }
            f1 = 1;
        }
        done0 = (f0 != 0);                    // volatile reads
        done1 = (f1 != 0);
        if (done0 && done1) break;
        a0 = b0; a1 = b1; base = nb;
    }

    // allow the dependent FFT kernel's prologue to overlap our tail
    asm volatile("griddepcontrol.launch_dependents;");
}

// ---------------------------------------------------------------------------
// Packed f32x2 helpers (Blackwell FFMA2 path — PTX only).
// ---------------------------------------------------------------------------
__device__ __forceinline__ u64 pk(float x, float y) {
    u64 u;
    asm("mov.b64 %0, {%1, %2};" : "=l"(u)
        : "r"(__float_as_uint(x)), "r"(__float_as_uint(y)));
    return u;
}
__device__ __forceinline__ u64 pk2(float2 a) { return pk(a.x, a.y); }
__device__ __forceinline__ float2 upk(u64 u) {
    unsigned lo, hi;
    asm("mov.b64 {%0, %1}, %2;" : "=r"(lo), "=r"(hi) : "l"(u));
    return make_float2(__uint_as_float(lo), __uint_as_float(hi));
}
__device__ __forceinline__ u64 padd(u64 a, u64 b) {
    u64 r; asm("add.rn.f32x2 %0, %1, %2;" : "=l"(r) : "l"(a), "l"(b)); return r;
}
__device__ __forceinline__ u64 pmul(u64 a, u64 b) {
    u64 r; asm("mul.rn.f32x2 %0, %1, %2;" : "=l"(r) : "l"(a), "l"(b)); return r;
}
__device__ __forceinline__ u64 pfma(u64 a, u64 b, u64 c) {
    u64 r; asm("fma.rn.f32x2 %0, %1, %2, %3;" : "=l"(r) : "l"(a), "l"(b), "l"(c)); return r;
}
__device__ __forceinline__ u64 psplat(float s) { return pk(s, s); }
__device__ __forceinline__ u64 psub(u64 a, u64 b) { return pfma(b, psplat(-1.0f), a); }
__device__ __forceinline__ u64 pcmul(u64 a, u64 b) {
    float2 af = upk(a), bf = upk(b);
    u64 u = pmul(pk(af.y, af.y), pk(bf.y, bf.x));   // {ay*by, ay*bx}
    float2 uf = upk(u);
    return pfma(pk(af.x, af.x), b, pk(-uf.x, uf.y));
}

// scalar complex helpers (Hermitian pass)
__device__ __forceinline__ float2 cmul(float2 a, float2 b) {
    return make_float2(a.x * b.x - a.y * b.y, a.x * b.y + a.y * b.x);
}

__device__ __constant__ int c_brev4[16] = {0,8,4,12,2,10,6,14,1,9,5,13,3,11,7,15};
__device__ __constant__ int c_brev3[8]  = {0,4,2,6,1,5,3,7};

// cheap small divisions (valid for the ranges used)
__device__ __forceinline__ int div5(int x)  { return (x * 205) >> 10; }   // x < 1024
__device__ __forceinline__ int div25(int x) { return (x * 41)  >> 10; }   // x < 600
__device__ __forceinline__ int mod125_16k(int x, int& q) {                // x <= 16000
    q = (int)(((unsigned)x * 8389u) >> 20);
    return x - q * 125;
}
__device__ __forceinline__ int digrev125(int b) {
    int d12 = div5(b);
    int d2  = div25(b);
    int d0  = b - d12 * 5;
    int d1  = d12 - d2 * 5;
    return d0 * 25 + d1 * 5 + d2;
}
__device__ __forceinline__ int brev7(int a) { return (int)(__brev((unsigned)a) >> 25); }

// ---------------------------------------------------------------------------
// Fused radix-2 butterfly blocks (DIF, logical t-order), packed arithmetic.
// ---------------------------------------------------------------------------
__device__ __forceinline__ void bfly16(u64* X, int j, const float2* W128) {
#pragma unroll
    for (int ls = 8; ls >= 1; ls >>= 1) {
        int f = 8 / ls;
#pragma unroll
        for (int g = 0; g < 8 / ls; g++)
#pragma unroll
            for (int i = 0; i < ls; i++) {
                int t0 = g * 2 * ls + i, t1 = t0 + ls;
                u64 u = X[t0], v = X[t1];
                X[t0] = padd(u, v);
                X[t1] = pcmul(psub(u, v), pk2(W128[(j + 8 * i) * f]));
            }
    }
}

__device__ __forceinline__ void bfly8(u64* X, const float2* W128) {
#pragma unroll
    for (int ls = 4; ls >= 1; ls >>= 1) {
        int f = 64 / ls;
#pragma unroll
        for (int g = 0; g < 4 / ls; g++)
#pragma unroll
            for (int i = 0; i < ls; i++) {
                int t0 = g * 2 * ls + i, t1 = t0 + ls;
                u64 u = X[t0], v = X[t1];
                X[t0] = padd(u, v);
                if (ls == 1) X[t1] = psub(u, v);
                else         X[t1] = pcmul(psub(u, v), pk2(W128[i * f]));
            }
    }
}

// Winograd-style radix-5 DFT, packed, with output twiddles W125[r*e].
__device__ __forceinline__ void bfly5(u64* x, int e, const float2* W125) {
    const float C1 = 0.30901699437494745f;   // cos(2pi/5)
    const float C2 = -0.8090169943749473f;   // cos(4pi/5)
    const float S1 = 0.9510565162951535f;    // sin(2pi/5)
    const float S2 = 0.5877852522924731f;    // sin(4pi/5)
    u64 t1 = padd(x[1], x[4]);
    u64 t2 = padd(x[2], x[3]);
    u64 t3 = psub(x[1], x[4]);
    u64 t4 = psub(x[2], x[3]);
    u64 y0 = padd(x[0], padd(t1, t2));
    u64 a1 = pfma(t1, psplat(C1), pfma(t2, psplat(C2), x[0]));
    u64 a2 = pfma(t1, psplat(C2), pfma(t2, psplat(C1), x[0]));
    u64 b1 = pfma(t3, psplat(S1), pmul(t4, psplat(S2)));
    u64 b2 = pfma(t3, psplat(S2), pmul(t4, psplat(-S1)));
    float2 b1f = upk(b1), b2f = upk(b2);
    u64 ib1 = pk(b1f.y, -b1f.x);             // -i * b1
    u64 ib2 = pk(b2f.y, -b2f.x);
    u64 y1 = padd(a1, ib1);
    u64 y4 = psub(a1, ib1);
    u64 y2 = padd(a2, ib2);
    u64 y3 = psub(a2, ib2);
    if (e) {
        y1 = pcmul(y1, pk2(W125[e]));
        y2 = pcmul(y2, pk2(W125[2 * e]));
        y3 = pcmul(y3, pk2(W125[3 * e]));
        y4 = pcmul(y4, pk2(W125[4 * e]));
    }
    x[0] = y0; x[1] = y1; x[2] = y2; x[3] = y3; x[4] = y4;
}

// fused stages m=5 (tw 5j) and m=1 over 25 register-resident values.
__device__ __forceinline__ void bfly25_m5_m1(u64* y, const float2* W125) {
#pragma unroll
    for (int j = 0; j < 5; j++) {
        u64 x[5];
#pragma unroll
        for (int r = 0; r < 5; r++) x[r] = y[j + 5 * r];
        bfly5(x, 5 * j, W125);
#pragma unroll
        for (int r = 0; r < 5; r++) y[j + 5 * r] = x[r];
    }
#pragma unroll
    for (int g = 0; g < 5; g++) {
        bfly5(&y[5 * g], 0, W125);
    }
}

// fused stages m=5 and m=1 in the sigma-permuted layout, local index i = 5j+s.
__device__ __forceinline__ void bfly25_m5_m1_perm(u64* y, const float2* W125) {
#pragma unroll
    for (int j = 0; j < 5; j++) {
        bfly5(&y[5 * j], 5 * j, W125);
    }
#pragma unroll
    for (int s = 0; s < 5; s++) {
        u64 x[5];
#pragma unroll
        for (int j = 0; j < 5; j++) x[j] = y[s + 5 * j];
        bfly5(x, 0, W125);
#pragma unroll
        for (int j = 0; j < 5; j++) y[s + 5 * j] = x[j];
    }
}

#define NTHR 1024

// ---------------------------------------------------------------------------
// Forward FFT2, natural layout in -> sigma-permuted out. 4 passes.
// ---------------------------------------------------------------------------
__device__ void fft2_nat(float2* Z, const float2* W128, const float2* W125,
                         int tid) {
    // a-axis group 1: stages 64,32,16,8
    {
        int j = tid >> 7, col = tid & 127;
        if (col < 125) {
            u64 X[16];
#pragma unroll
            for (int t = 0; t < 16; t++) X[t] = pk2(Z[(j + 8 * t) * 125 + col]);
            bfly16(X, j, W128);
#pragma unroll
            for (int t = 0; t < 16; t++) Z[(j + 8 * t) * 125 + col] = upk(X[t]);
        }
    }
    __syncthreads();
    // a-axis group 2: stages 4,2,1
#pragma unroll
    for (int it = 0; it < 2; it++) {
        int idx = tid + it * NTHR;
        int g = idx >> 7, col = idx & 127;
        if (col < 125) {
            u64 X[8];
#pragma unroll
            for (int t = 0; t < 8; t++) X[t] = pk2(Z[(8 * g + t) * 125 + col]);
            bfly8(X, W128);
#pragma unroll
            for (int t = 0; t < 8; t++) Z[(8 * g + t) * 125 + col] = upk(X[t]);
        }
    }
    __syncthreads();
    // b-axis m=25: 128 a x 25 c
#pragma unroll
    for (int it = 0; it < 4; it++) {
        int idx = tid + it * NTHR;
        int a = idx >> 5, c = idx & 31;
        if (c < 25) {
            int base = a * 125 + c;
            u64 x[5];
#pragma unroll
            for (int r = 0; r < 5; r++) x[r] = pk2(Z[base + 25 * r]);
            bfly5(x, c, W125);
#pragma unroll
            for (int r = 0; r < 5; r++) Z[base + 25 * r] = upk(x[r]);
        }
    }
    __syncthreads();
    // b-axis fused m=5 & m=1: lane <-> a, warp-uniform t
    {
        int u = tid;
        if (u < 640) {
            int a = u & 127, t = u >> 7;
            int base = a * 125 + t * 25;
            u64 y[25];
#pragma unroll
            for (int i = 0; i < 25; i++) y[i] = pk2(Z[base + i]);
            bfly25_m5_m1(y, W125);
#pragma unroll
            for (int i = 0; i < 25; i++) Z[base + i] = upk(y[i]);
        }
    }
    __syncthreads();
}

// ---------------------------------------------------------------------------
// Kernel F: one CTA per batch row. PDL: waits for extract AFTER its prologue.
// ---------------------------------------------------------------------------
__global__ void __launch_bounds__(NTHR, 1)
mcb_fft_kernel(const float* __restrict__ x1,
               const float* __restrict__ x2,
               float* __restrict__ out) {
    extern __shared__ float2 sm[];
    float2* Z    = sm;                       // 16000
    float2* W128 = sm + 16000;               // 128
    float2* W125 = sm + 16128;               // 125
    float*  sOut = (float*)(sm + 16254);     // 16000 floats, 16B-aligned

    const int tid = threadIdx.x;
    const int row = blockIdx.x;

    // init: zero grid (float4), fill twiddle tables — independent of extract
    float4* Z4 = (float4*)Z;
#pragma unroll
    for (int it = 0; it < 8; it++) {
        int i = tid + it * NTHR;
        if (i < 8000) Z4[i] = make_float4(0.f, 0.f, 0.f, 0.f);
    }
    if (tid < 128) {
        float s, c;
        sincosf(-6.283185307179586f * (float)tid / 128.f, &s, &c);
        W128[tid] = make_float2(c, s);
    }
    {
        int k = tid - 128;
        if (k >= 0 && k < 125) {
            float s, c;
            sincosf(-6.283185307179586f * (float)k / 125.f, &s, &c);
            W125[k] = make_float2(c, s);
        }
    }

    // PDL: block here until the extract grid's writes are visible.
    asm volatile("griddepcontrol.wait;" ::: "memory");
    __syncthreads();

    // count-sketch scatter onto CRT-mapped 2-D grid (natural layout)
    const float* x1r = x1 + row * DD;
    const float* x2r = x2 + row * DD;
#pragma unroll
    for (int it = 0; it < 2; it++) {
        int d = tid + it * NTHR;
        int q1, q2;
        int n1 = g_idx1[d];
        float v1 = g_sgn1[d] * x1r[d];
        int b1 = mod125_16k(n1, q1);
        atomicAdd(&Z[(n1 & 127) * 125 + b1].x, v1);
        int n2 = g_idx2[d];
        float v2 = g_sgn2[d] * x2r[d];
        int b2 = mod125_16k(n2, q2);
        atomicAdd(&Z[(n2 & 127) * 125 + b2].y, v2);
    }
    __syncthreads();

    // forward FFT2 of z = y1 + i*y2; physical slot p holds Fz[sigma(p)]
    fft2_nat(Z, W128, W125, tid);

    // Hermitian unpack + pointwise product, enumerating LOGICAL k in [0, 8000].
    for (int k = tid; k <= 8000; k += NTHR) {
        int ka = k & 127;
        int q;
        int kb = mod125_16k(k, q);
        int p  = brev7(ka) * 125 + digrev125(kb);
        int kam = (128 - ka) & 127;
        int kbm = (kb == 0) ? 0 : 125 - kb;
        int pm  = brev7(kam) * 125 + digrev125(kbm);
        float2 zk = Z[p], zm = Z[pm];
        float2 f1 = make_float2(0.5f * (zk.x + zm.x),  0.5f * (zk.y - zm.y));
        float2 f2 = make_float2(0.5f * (zk.y + zm.y), -0.5f * (zk.x - zm.x));
        float2 g  = cmul(f1, f2);
        Z[p]  = make_float2(g.x, -g.y);     // conj(G[k])
        Z[pm] = g;                          // conj(G[-k]) = G[k]
    }
    __syncthreads();

    // ---- inverse via forward-on-conj in the sigma-permuted layout ----
    // a-axis group 1: logical rows j+8t at physical brev3(j)*16 + brev4(t)
    {
        int j = tid >> 7, col = tid & 127;
        if (col < 125) {
            int R0 = c_brev3[j] * 16;
            u64 X[16];
#pragma unroll
            for (int t = 0; t < 16; t++) X[t] = pk2(Z[(R0 + c_brev4[t]) * 125 + col]);
            bfly16(X, j, W128);
#pragma unroll
            for (int t = 0; t < 16; t++) Z[(R0 + c_brev4[t]) * 125 + col] = upk(X[t]);
        }
    }
    __syncthreads();
    // a-axis group 2: logical rows 8g+t at physical brev3(t)*16 + brev4(g)
#pragma unroll
    for (int it = 0; it < 2; it++) {
        int idx = tid + it * NTHR;
        int g = idx >> 7, col = idx & 127;
        if (col < 125) {
            int G = c_brev4[g];
            u64 X[8];
#pragma unroll
            for (int t = 0; t < 8; t++) X[t] = pk2(Z[(c_brev3[t] * 16 + G) * 125 + col]);
            bfly8(X, W128);
#pragma unroll
            for (int t = 0; t < 8; t++) Z[(c_brev3[t] * 16 + G) * 125 + col] = upk(X[t]);
        }
    }
    __syncthreads();
    // b-axis m=25: logical b = c + 25t -> physical (c%5)*25 + (c/5)*5 + t
#pragma unroll
    for (int it = 0; it < 4; it++) {
        int idx = tid + it * NTHR;
        int a = idx >> 5, c = idx & 31;
        if (c < 25) {
            int ch = div5(c), cl = c - ch * 5;
            int base = a * 125 + cl * 25 + ch * 5;
            u64 x[5];
#pragma unroll
            for (int r = 0; r < 5; r++) x[r] = pk2(Z[base + r]);
            bfly5(x, c, W125);
#pragma unroll
            for (int r = 0; r < 5; r++) Z[base + r] = upk(x[r]);
        }
    }
    __syncthreads();
    // b-axis fused m=5 & m=1; stage real part into sOut at natural CRT index.
    // lane <-> a mapping: 10625 % 32 == 1 -> sOut banks consecutive per lane.
    {
        const float scale = 1.0f / 16000.0f;
        int u = tid;
        if (u < 640) {
            int a = u & 127, t = u >> 7;
            int base = a * 125 + t;
            u64 y[25];
#pragma unroll
            for (int i = 0; i < 25; i++) y[i] = pk2(Z[base + 5 * i]);
            bfly25_m5_m1_perm(y, W125);
            int n = (a * 10625 + t * 5376) % 16000;
#pragma unroll
            for (int i = 0; i < 25; i++) {
                sOut[n] = upk(y[i]).x * scale;
                n += 10880;
                if (n >= 16000) n -= 16000;
            }
        }
    }
    __syncthreads();

    // coalesced output write
    {
        const float4* so4 = (const float4*)sOut;
        float4* og = (float4*)(out + row * PP);
#pragma unroll
        for (int it = 0; it < 4; it++) {
            int i = tid + it * NTHR;
            if (i < 4000) og[i] = so4[i];
        }
    }
}

// ---------------------------------------------------------------------------
// Launch (PDL: FFT kernel launched with programmatic stream serialization)
// ---------------------------------------------------------------------------
extern "C" void kernel_launch(void* const* d_in, const int* in_sizes, int n_in,
                              void* d_out, int out_size) {
    const float*  x1 = (const float*)d_in[0];
    const float*  x2 = (const float*)d_in[1];
    const float4* C1 = (const float4*)d_in[2];
    const float4* C2 = (const float4*)d_in[3];
    float* out = (float*)d_out;

    const int B = in_sizes[0] / DD;           // 128

    extract_kernel<<<DD, 256>>>(C1, C2);      // 2048 CTAs, 2 rows each

    const size_t smem = (size_t)16254 * sizeof(float2) + (size_t)PP * sizeof(float); // 194,032 B
    cudaFuncSetAttribute(mcb_fft_kernel,
                         cudaFuncAttributeMaxDynamicSharedMemorySize, (int)smem);

    cudaLaunchConfig_t cfg = {};
    cfg.gridDim = dim3(B, 1, 1);
    cfg.blockDim = dim3(NTHR, 1, 1);
    cfg.dynamicSmemBytes = smem;
    cudaLaunchAttribute attrs[1];
    attrs[0].id = cudaLaunchAttributeProgrammaticStreamSerialization;
    attrs[0].val.programmaticStreamSerializationAllowed = 1;
    cfg.attrs = attrs;
    cfg.numAttrs = 1;
    cudaLaunchKernelEx(&cfg, mcb_fft_kernel, x1, x2, out);
}

// round 16
// speedup vs baseline: 1.0361x; 1.0281x over previous
#include <cuda_runtime.h>

#define DD 2048
#define PP 16000

typedef unsigned long long u64;

// Sketch structure extracted from C1/C2 each launch (deterministic).
__device__ int   g_idx1[DD], g_idx2[DD];
__device__ float g_sgn1[DD], g_sgn2[DD];

// ---------------------------------------------------------------------------
// Kernel E: one 256-thread CTA scans TWO C-rows concurrently (interleaved
// independent load streams -> 2x memory-level parallelism at equal bytes).
// Early-exit per row via volatile shared flags; one nonzero per row ->
// single writer, flag races benign. PDL launch_dependents at CTA START so
// the dependent FFT kernel's prologue overlaps the extract tail.
// ---------------------------------------------------------------------------
__global__ void __launch_bounds__(256)
extract_kernel(const float4* __restrict__ C1, const float4* __restrict__ C2) {
    // Let dependents launch as soon as the whole primary grid is resident;
    // their griddepcontrol.wait still fences our writes.
    asm volatile("griddepcontrol.launch_dependents;");

    int pair = blockIdx.x;                    // 0..2047
    int d0 = 2 * pair, d1 = 2 * pair + 1;     // rows 0..4095

    const float4 *rp0, *rp1;
    int *ix0, *ix1;
    float *sg0, *sg1;
    int r0, r1;
    if (d0 < DD) { rp0 = C1 + (size_t)d0 * 4000;        ix0 = g_idx1; sg0 = g_sgn1; r0 = d0; }
    else         { rp0 = C2 + (size_t)(d0 - DD) * 4000; ix0 = g_idx2; sg0 = g_sgn2; r0 = d0 - DD; }
    if (d1 < DD) { rp1 = C1 + (size_t)d1 * 4000;        ix1 = g_idx1; sg1 = g_sgn1; r1 = d1; }
    else         { rp1 = C2 + (size_t)(d1 - DD) * 4000; ix1 = g_idx2; sg1 = g_sgn2; r1 = d1 - DD; }

    volatile __shared__ int f0, f1;
    if (threadIdx.x == 0) { f0 = 0; f1 = 0; }
    __syncthreads();

    // 4000 float4 per row; 16 chunks of 256 float4 per row, depth-1 prefetch.
    int base = threadIdx.x;
    float4 a0 = __ldcs(&rp0[base]);
    float4 a1 = __ldcs(&rp1[base]);
    bool done0 = false, done1 = false;
#pragma unroll 1
    for (int c = 0; c < 16; c++) {
        int nb = base + 256;
        float4 b0 = make_float4(0.f, 0.f, 0.f, 0.f);
        float4 b1 = make_float4(0.f, 0.f, 0.f, 0.f);
        if (c < 15 && nb < 4000) {
            if (!done0) b0 = __ldcs(&rp0[nb]);
            if (!done1) b1 = __ldcs(&rp1[nb]);
        }
        if (!done0 && base < 4000 &&
            (a0.x != 0.f || a0.y != 0.f || a0.z != 0.f || a0.w != 0.f)) {
            int e = base * 4;
            if      (a0.x != 0.f) { ix0[r0] = e;     sg0[r0] = a0.x; }
            else if (a0.y != 0.f) { ix0[r0] = e + 1; sg0[r0] = a0.y; }
            else if (a0.z != 0.f) { ix0[r0] = e + 2; sg0[r0] = a0.z; }
            else                  { ix0[r0] = e + 3; sg0[r0] = a0.w; }
            f0 = 1;
        }
        if (!done1 && base < 4000 &&
            (a1.x != 0.f || a1.y != 0.f || a1.z != 0.f || a1.w != 0.f)) {
            int e = base * 4;
            if      (a1.x != 0.f) { ix1[r1] = e;     sg1[r1] = a1.x; }
            else if (a1.y != 0.f) { ix1[r1] = e + 1; sg1[r1] = a1.y; }
            else if (a1.z != 0.f) { ix1[r1] = e + 2; sg1[r1] = a1.z; }
            else                  { ix1[r1] = e + 3; sg1[r1] = a1.w; }
            f1 = 1;
        }
        done0 = (f0 != 0);                    // volatile reads
        done1 = (f1 != 0);
        if (done0 && done1) break;
        a0 = b0; a1 = b1; base = nb;
    }
}

// ---------------------------------------------------------------------------
// Packed f32x2 helpers (Blackwell FFMA2 path — PTX only).
// ---------------------------------------------------------------------------
__device__ __forceinline__ u64 pk(float x, float y) {
    u64 u;
    asm("mov.b64 %0, {%1, %2};" : "=l"(u)
        : "r"(__float_as_uint(x)), "r"(__float_as_uint(y)));
    return u;
}
__device__ __forceinline__ u64 pk2(float2 a) { return pk(a.x, a.y); }
__device__ __forceinline__ float2 upk(u64 u) {
    unsigned lo, hi;
    asm("mov.b64 {%0, %1}, %2;" : "=r"(lo), "=r"(hi) : "l"(u));
    return make_float2(__uint_as_float(lo), __uint_as_float(hi));
}
__device__ __forceinline__ u64 padd(u64 a, u64 b) {
    u64 r; asm("add.rn.f32x2 %0, %1, %2;" : "=l"(r) : "l"(a), "l"(b)); return r;
}
__device__ __forceinline__ u64 pmul(u64 a, u64 b) {
    u64 r; asm("mul.rn.f32x2 %0, %1, %2;" : "=l"(r) : "l"(a), "l"(b)); return r;
}
__device__ __forceinline__ u64 pfma(u64 a, u64 b, u64 c) {
    u64 r; asm("fma.rn.f32x2 %0, %1, %2, %3;" : "=l"(r) : "l"(a), "l"(b), "l"(c)); return r;
}
__device__ __forceinline__ u64 psplat(float s) { return pk(s, s); }
__device__ __forceinline__ u64 psub(u64 a, u64 b) { return pfma(b, psplat(-1.0f), a); }
__device__ __forceinline__ u64 pcmul(u64 a, u64 b) {
    float2 af = upk(a), bf = upk(b);
    u64 u = pmul(pk(af.y, af.y), pk(bf.y, bf.x));   // {ay*by, ay*bx}
    float2 uf = upk(u);
    return pfma(pk(af.x, af.x), b, pk(-uf.x, uf.y));
}

// scalar complex helpers (Hermitian pass)
__device__ __forceinline__ float2 cmul(float2 a, float2 b) {
    return make_float2(a.x * b.x - a.y * b.y, a.x * b.y + a.y * b.x);
}

__device__ __constant__ int c_brev4[16] = {0,8,4,12,2,10,6,14,1,9,5,13,3,11,7,15};
__device__ __constant__ int c_brev3[8]  = {0,4,2,6,1,5,3,7};

// cheap small divisions (valid for the ranges used)
__device__ __forceinline__ int div5(int x)   { return (x * 205) >> 10; }    // x < 1024
__device__ __forceinline__ int div25(int x)  { return (x * 41)  >> 10; }    // x < 600
__device__ __forceinline__ int div25b(int x) { return (x * 10486) >> 18; }  // x <= 3200
__device__ __forceinline__ int mod125_16k(int x, int& q) {                  // x <= 16000
    q = (int)(((unsigned)x * 8389u) >> 20);
    return x - q * 125;
}
__device__ __forceinline__ int digrev125(int b) {
    int d12 = div5(b);
    int d2  = div25(b);
    int d0  = b - d12 * 5;
    int d1  = d12 - d2 * 5;
    return d0 * 25 + d1 * 5 + d2;
}
__device__ __forceinline__ int brev7(int a) { return (int)(__brev((unsigned)a) >> 25); }

// ---------------------------------------------------------------------------
// Fused radix-2 butterfly blocks (DIF, logical t-order), packed arithmetic.
// ---------------------------------------------------------------------------
__device__ __forceinline__ void bfly16(u64* X, int j, const float2* W128) {
#pragma unroll
    for (int ls = 8; ls >= 1; ls >>= 1) {
        int f = 8 / ls;
#pragma unroll
        for (int g = 0; g < 8 / ls; g++)
#pragma unroll
            for (int i = 0; i < ls; i++) {
                int t0 = g * 2 * ls + i, t1 = t0 + ls;
                u64 u = X[t0], v = X[t1];
                X[t0] = padd(u, v);
                X[t1] = pcmul(psub(u, v), pk2(W128[(j + 8 * i) * f]));
            }
    }
}

__device__ __forceinline__ void bfly8(u64* X, const float2* W128) {
#pragma unroll
    for (int ls = 4; ls >= 1; ls >>= 1) {
        int f = 64 / ls;
#pragma unroll
        for (int g = 0; g < 4 / ls; g++)
#pragma unroll
            for (int i = 0; i < ls; i++) {
                int t0 = g * 2 * ls + i, t1 = t0 + ls;
                u64 u = X[t0], v = X[t1];
                X[t0] = padd(u, v);
                if (ls == 1) X[t1] = psub(u, v);
                else         X[t1] = pcmul(psub(u, v), pk2(W128[i * f]));
            }
    }
}

// Winograd-style radix-5 DFT, packed, with output twiddles W125[r*e].
__device__ __forceinline__ void bfly5(u64* x, int e, const float2* W125) {
    const float C1 = 0.30901699437494745f;   // cos(2pi/5)
    const float C2 = -0.8090169943749473f;   // cos(4pi/5)
    const float S1 = 0.9510565162951535f;    // sin(2pi/5)
    const float S2 = 0.5877852522924731f;    // sin(4pi/5)
    u64 t1 = padd(x[1], x[4]);
    u64 t2 = padd(x[2], x[3]);
    u64 t3 = psub(x[1], x[4]);
    u64 t4 = psub(x[2], x[3]);
    u64 y0 = padd(x[0], padd(t1, t2));
    u64 a1 = pfma(t1, psplat(C1), pfma(t2, psplat(C2), x[0]));
    u64 a2 = pfma(t1, psplat(C2), pfma(t2, psplat(C1), x[0]));
    u64 b1 = pfma(t3, psplat(S1), pmul(t4, psplat(S2)));
    u64 b2 = pfma(t3, psplat(S2), pmul(t4, psplat(-S1)));
    float2 b1f = upk(b1), b2f = upk(b2);
    u64 ib1 = pk(b1f.y, -b1f.x);             // -i * b1
    u64 ib2 = pk(b2f.y, -b2f.x);
    u64 y1 = padd(a1, ib1);
    u64 y4 = psub(a1, ib1);
    u64 y2 = padd(a2, ib2);
    u64 y3 = psub(a2, ib2);
    if (e) {
        y1 = pcmul(y1, pk2(W125[e]));
        y2 = pcmul(y2, pk2(W125[2 * e]));
        y3 = pcmul(y3, pk2(W125[3 * e]));
        y4 = pcmul(y4, pk2(W125[4 * e]));
    }
    x[0] = y0; x[1] = y1; x[2] = y2; x[3] = y3; x[4] = y4;
}

// fused stages m=5 (tw 5j) and m=1 over 25 register-resident values.
__device__ __forceinline__ void bfly25_m5_m1(u64* y, const float2* W125) {
#pragma unroll
    for (int j = 0; j < 5; j++) {
        u64 x[5];
#pragma unroll
        for (int r = 0; r < 5; r++) x[r] = y[j + 5 * r];
        bfly5(x, 5 * j, W125);
#pragma unroll
        for (int r = 0; r < 5; r++) y[j + 5 * r] = x[r];
    }
#pragma unroll
    for (int g = 0; g < 5; g++) {
        bfly5(&y[5 * g], 0, W125);
    }
}

// fused stages m=5 and m=1 in the sigma-permuted layout, local index i = 5j+s.
__device__ __forceinline__ void bfly25_m5_m1_perm(u64* y, const float2* W125) {
#pragma unroll
    for (int j = 0; j < 5; j++) {
        bfly5(&y[5 * j], 5 * j, W125);
    }
#pragma unroll
    for (int s = 0; s < 5; s++) {
        u64 x[5];
#pragma unroll
        for (int j = 0; j < 5; j++) x[j] = y[s + 5 * j];
        bfly5(x, 0, W125);
#pragma unroll
        for (int j = 0; j < 5; j++) y[s + 5 * j] = x[j];
    }
}

#define NTHR 1024

// ---------------------------------------------------------------------------
// Forward FFT2, natural layout in -> sigma-permuted out. 4 passes.
// ---------------------------------------------------------------------------
__device__ void fft2_nat(float2* Z, const float2* W128, const float2* W125,
                         int tid) {
    // a-axis group 1: stages 64,32,16,8
    {
        int j = tid >> 7, col = tid & 127;
        if (col < 125) {
            u64 X[16];
#pragma unroll
            for (int t = 0; t < 16; t++) X[t] = pk2(Z[(j + 8 * t) * 125 + col]);
            bfly16(X, j, W128);
#pragma unroll
            for (int t = 0; t < 16; t++) Z[(j + 8 * t) * 125 + col] = upk(X[t]);
        }
    }
    __syncthreads();
    // a-axis group 2: stages 4,2,1
#pragma unroll
    for (int it = 0; it < 2; it++) {
        int idx = tid + it * NTHR;
        int g = idx >> 7, col = idx & 127;
        if (col < 125) {
            u64 X[8];
#pragma unroll
            for (int t = 0; t < 8; t++) X[t] = pk2(Z[(8 * g + t) * 125 + col]);
            bfly8(X, W128);
#pragma unroll
            for (int t = 0; t < 8; t++) Z[(8 * g + t) * 125 + col] = upk(X[t]);
        }
    }
    __syncthreads();
    // b-axis m=25: 3200 compact units (all lanes active)
#pragma unroll
    for (int it = 0; it < 4; it++) {
        int u = tid + it * NTHR;
        if (u < 3200) {
            int a = div25b(u);
            int c = u - a * 25;
            int base = a * 125 + c;
            u64 x[5];
#pragma unroll
            for (int r = 0; r < 5; r++) x[r] = pk2(Z[base + 25 * r]);
            bfly5(x, c, W125);
#pragma unroll
            for (int r = 0; r < 5; r++) Z[base + 25 * r] = upk(x[r]);
        }
    }
    __syncthreads();
    // b-axis fused m=5 & m=1: lane <-> a, warp-uniform t
    {
        int u = tid;
        if (u < 640) {
            int a = u & 127, t = u >> 7;
            int base = a * 125 + t * 25;
            u64 y[25];
#pragma unroll
            for (int i = 0; i < 25; i++) y[i] = pk2(Z[base + i]);
            bfly25_m5_m1(y, W125);
#pragma unroll
            for (int i = 0; i < 25; i++) Z[base + i] = upk(y[i]);
        }
    }
    __syncthreads();
}

// ---------------------------------------------------------------------------
// Kernel F: one CTA per batch row. PDL: waits for extract AFTER its prologue.
// ---------------------------------------------------------------------------
__global__ void __launch_bounds__(NTHR, 1)
mcb_fft_kernel(const float* __restrict__ x1,
               const float* __restrict__ x2,
               float* __restrict__ out) {
    extern __shared__ float2 sm[];
    float2* Z    = sm;                       // 16000
    float2* W128 = sm + 16000;               // 128
    float2* W125 = sm + 16128;               // 125
    float*  sOut = (float*)(sm + 16254);     // 16000 floats, 16B-aligned

    const int tid = threadIdx.x;
    const int row = blockIdx.x;

    // init: zero grid (float4), fill twiddle tables — independent of extract
    float4* Z4 = (float4*)Z;
#pragma unroll
    for (int it = 0; it < 8; it++) {
        int i = tid + it * NTHR;
        if (i < 8000) Z4[i] = make_float4(0.f, 0.f, 0.f, 0.f);
    }
    if (tid < 128) {
        float s, c;
        sincosf(-6.283185307179586f * (float)tid / 128.f, &s, &c);
        W128[tid] = make_float2(c, s);
    }
    {
        int k = tid - 128;
        if (k >= 0 && k < 125) {
            float s, c;
            sincosf(-6.283185307179586f * (float)k / 125.f, &s, &c);
            W125[k] = make_float2(c, s);
        }
    }

    // PDL: block here until the extract grid's writes are visible.
    asm volatile("griddepcontrol.wait;" ::: "memory");
    __syncthreads();

    // count-sketch scatter onto CRT-mapped 2-D grid (natural layout)
    const float* x1r = x1 + row * DD;
    const float* x2r = x2 + row * DD;
#pragma unroll
    for (int it = 0; it < 2; it++) {
        int d = tid + it * NTHR;
        int q1, q2;
        int n1 = g_idx1[d];
        float v1 = g_sgn1[d] * x1r[d];
        int b1 = mod125_16k(n1, q1);
        atomicAdd(&Z[(n1 & 127) * 125 + b1].x, v1);
        int n2 = g_idx2[d];
        float v2 = g_sgn2[d] * x2r[d];
        int b2 = mod125_16k(n2, q2);
        atomicAdd(&Z[(n2 & 127) * 125 + b2].y, v2);
    }
    __syncthreads();

    // forward FFT2 of z = y1 + i*y2; physical slot p holds Fz[sigma(p)]
    fft2_nat(Z, W128, W125, tid);

    // Hermitian unpack + pointwise product, enumerating LOGICAL k in [0, 8000].
    for (int k = tid; k <= 8000; k += NTHR) {
        int ka = k & 127;
        int q;
        int kb = mod125_16k(k, q);
        int p  = brev7(ka) * 125 + digrev125(kb);
        int kam = (128 - ka) & 127;
        int kbm = (kb == 0) ? 0 : 125 - kb;
        int pm  = brev7(kam) * 125 + digrev125(kbm);
        float2 zk = Z[p], zm = Z[pm];
        float2 f1 = make_float2(0.5f * (zk.x + zm.x),  0.5f * (zk.y - zm.y));
        float2 f2 = make_float2(0.5f * (zk.y + zm.y), -0.5f * (zk.x - zm.x));
        float2 g  = cmul(f1, f2);
        Z[p]  = make_float2(g.x, -g.y);     // conj(G[k])
        Z[pm] = g;                          // conj(G[-k]) = G[k]
    }
    __syncthreads();

    // ---- inverse via forward-on-conj in the sigma-permuted layout ----
    // a-axis group 1: logical rows j+8t at physical brev3(j)*16 + brev4(t)
    {
        int j = tid >> 7, col = tid & 127;
        if (col < 125) {
            int R0 = c_brev3[j] * 16;
            u64 X[16];
#pragma unroll
            for (int t = 0; t < 16; t++) X[t] = pk2(Z[(R0 + c_brev4[t]) * 125 + col]);
            bfly16(X, j, W128);
#pragma unroll
            for (int t = 0; t < 16; t++) Z[(R0 + c_brev4[t]) * 125 + col] = upk(X[t]);
        }
    }
    __syncthreads();
    // a-axis group 2: logical rows 8g+t at physical brev3(t)*16 + brev4(g)
#pragma unroll
    for (int it = 0; it < 2; it++) {
        int idx = tid + it * NTHR;
        int g = idx >> 7, col = idx & 127;
        if (col < 125) {
            int G = c_brev4[g];
            u64 X[8];
#pragma unroll
            for (int t = 0; t < 8; t++) X[t] = pk2(Z[(c_brev3[t] * 16 + G) * 125 + col]);
            bfly8(X, W128);
#pragma unroll
            for (int t = 0; t < 8; t++) Z[(c_brev3[t] * 16 + G) * 125 + col] = upk(X[t]);
        }
    }
    __syncthreads();
    // b-axis m=25 (perm): 3200 compact units (all lanes active)
    // logical b = c + 25t -> physical (c%5)*25 + (c/5)*5 + t
#pragma unroll
    for (int it = 0; it < 4; it++) {
        int u = tid + it * NTHR;
        if (u < 3200) {
            int a = div25b(u);
            int c = u - a * 25;
            int ch = div5(c), cl = c - ch * 5;
            int base = a * 125 + cl * 25 + ch * 5;
            u64 x[5];
#pragma unroll
            for (int r = 0; r < 5; r++) x[r] = pk2(Z[base + r]);
            bfly5(x, c, W125);
#pragma unroll
            for (int r = 0; r < 5; r++) Z[base + r] = upk(x[r]);
        }
    }
    __syncthreads();
    // b-axis fused m=5 & m=1; stage real part into sOut at natural CRT index.
    // lane <-> a mapping: 10625 % 32 == 1 -> sOut banks consecutive per lane.
    {
        const float scale = 1.0f / 16000.0f;
        int u = tid;
        if (u < 640) {
            int a = u & 127, t = u >> 7;
            int base = a * 125 + t;
            u64 y[25];
#pragma unroll
            for (int i = 0; i < 25; i++) y[i] = pk2(Z[base + 5 * i]);
            bfly25_m5_m1_perm(y, W125);
            int n = (a * 10625 + t * 5376) % 16000;
#pragma unroll
            for (int i = 0; i < 25; i++) {
                sOut[n] = upk(y[i]).x * scale;
                n += 10880;
                if (n >= 16000) n -= 16000;
            }
        }
    }
    __syncthreads();

    // coalesced output write
    {
        const float4* so4 = (const float4*)sOut;
        float4* og = (float4*)(out + row * PP);
#pragma unroll
        for (int it = 0; it < 4; it++) {
            int i = tid + it * NTHR;
            if (i < 4000) og[i] = so4[i];
        }
    }
}

// ---------------------------------------------------------------------------
// Launch (PDL: FFT kernel launched with programmatic stream serialization)
// ---------------------------------------------------------------------------
extern "C" void kernel_launch(void* const* d_in, const int* in_sizes, int n_in,
                              void* d_out, int out_size) {
    const float*  x1 = (const float*)d_in[0];
    const float*  x2 = (const float*)d_in[1];
    const float4* C1 = (const float4*)d_in[2];
    const float4* C2 = (const float4*)d_in[3];
    float* out = (float*)d_out;

    const int B = in_sizes[0] / DD;           // 128

    extract_kernel<<<DD, 256>>>(C1, C2);      // 2048 CTAs, 2 rows each

    const size_t smem = (size_t)16254 * sizeof(float2) + (size_t)PP * sizeof(float); // 194,032 B
    cudaFuncSetAttribute(mcb_fft_kernel,
                         cudaFuncAttributeMaxDynamicSharedMemorySize, (int)smem);

    cudaLaunchConfig_t cfg = {};
    cfg.gridDim = dim3(B, 1, 1);
    cfg.blockDim = dim3(NTHR, 1, 1);
    cfg.dynamicSmemBytes = smem;
    cudaLaunchAttribute attrs[1];
    attrs[0].id = cudaLaunchAttributeProgrammaticStreamSerialization;
    attrs[0].val.programmaticStreamSerializationAllowed = 1;
    cfg.attrs = attrs;
    cfg.numAttrs = 1;
    cudaLaunchKernelEx(&cfg, mcb_fft_kernel, x1, x2, out);
}